// round 1
// baseline (speedup 1.0000x reference)
#include <cuda_runtime.h>
#include <cuda_bf16.h>

// Problem: CrossBaby_1  (B=32, S=128, V=8192, E=256)
// Pipeline (matches reference's reassociated math):
//   h    = relu(x @ w_emb^T + b_emb)                 [B*S, E]
//   s    = sum_e h                                    [B, S]  (stored transposed [S][B])
//   Weff[b,e,j] = sum_k w_red[e, k*E+j] * s[b,k]      [B, E, E]
//   y    = relu(batched h_b @ Weff_b^T + b_red)       [B, S, E]
//   y2   = relu(y.flat @ w_red2^T + b_red2)           [B, E]   (split-K + reduce)
//   out  = y2 @ w_out^T + b_out                       [B, V]

#define B_  32
#define S_  128
#define V_  8192
#define E_  256

// ---------------- scratch (static device globals; no allocation) ------------
__device__ float g_h   [B_ * S_ * E_];        // 1M floats
__device__ float g_st  [S_ * B_];             // s transposed: [k][b]
__device__ float g_weff[B_ * E_ * E_];        // 2M floats
__device__ float g_y   [B_ * S_ * E_];        // 1M floats
__device__ float g_part[128 * B_ * E_];       // split-K partials for y2
__device__ float g_y2  [B_ * E_];

// ---------------- generic NT GEMM ------------------------------------------
// C[z][m][n] = op( sum_k A[z][m][k] * B[z][n][k] + bias[n] )
// A row-major with row stride lda, batch stride strideAz (likewise B, C).
// Register-prefetched double-stage pipeline (load tile t+1 into regs while
// computing tile t from smem). Requires M%BM==0, N%BN==0, K%BK==0.
template<int BM, int BN, int BK, int TM, int TN>
__global__ void gemm_nt_kernel(const float* __restrict__ A, int lda, long sAz,
                               const float* __restrict__ B, int ldb, long sBz,
                               float* __restrict__ C, int ldc, long sCz,
                               const float* __restrict__ bias,
                               int K, int do_relu)
{
    constexpr int THREADS = (BM * BN) / (TM * TN);
    constexpr int LA = (BM * BK) / THREADS;
    constexpr int LB = (BN * BK) / THREADS;
    constexpr int TX = BN / TN;             // threads along n

    __shared__ float As[BK][BM + 4];
    __shared__ float Bs[BK][BN + 4];

    const long z = blockIdx.z;
    A += z * sAz;  B += z * sBz;  C += z * sCz;

    const int m0 = blockIdx.x * BM;
    const int n0 = blockIdx.y * BN;
    const int tid = threadIdx.x;
    const int tx = tid % TX;                // n tile coord
    const int ty = tid / TX;                // m tile coord

    float acc[TM][TN];
    #pragma unroll
    for (int i = 0; i < TM; i++)
        #pragma unroll
        for (int j = 0; j < TN; j++) acc[i][j] = 0.f;

    float ra[LA], rb[LB];
    const int nTiles = K / BK;

    // prologue: load tile 0 into regs, then smem
    #pragma unroll
    for (int u = 0; u < LA; u++) {
        int idx = tid + u * THREADS;
        ra[u] = A[(long)(m0 + idx / BK) * lda + (idx % BK)];
    }
    #pragma unroll
    for (int u = 0; u < LB; u++) {
        int idx = tid + u * THREADS;
        rb[u] = B[(long)(n0 + idx / BK) * ldb + (idx % BK)];
    }
    #pragma unroll
    for (int u = 0; u < LA; u++) {
        int idx = tid + u * THREADS;
        As[idx % BK][idx / BK] = ra[u];
    }
    #pragma unroll
    for (int u = 0; u < LB; u++) {
        int idx = tid + u * THREADS;
        Bs[idx % BK][idx / BK] = rb[u];
    }
    __syncthreads();

    for (int t = 0; t < nTiles; t++) {
        const int k_next = (t + 1) * BK;
        const bool have_next = (t + 1) < nTiles;
        if (have_next) {
            #pragma unroll
            for (int u = 0; u < LA; u++) {
                int idx = tid + u * THREADS;
                ra[u] = A[(long)(m0 + idx / BK) * lda + k_next + (idx % BK)];
            }
            #pragma unroll
            for (int u = 0; u < LB; u++) {
                int idx = tid + u * THREADS;
                rb[u] = B[(long)(n0 + idx / BK) * ldb + k_next + (idx % BK)];
            }
        }

        #pragma unroll
        for (int kk = 0; kk < BK; kk++) {
            float a[TM], b[TN];
            #pragma unroll
            for (int i = 0; i < TM; i++) a[i] = As[kk][ty * TM + i];
            #pragma unroll
            for (int j = 0; j < TN; j++) b[j] = Bs[kk][tx * TN + j];
            #pragma unroll
            for (int i = 0; i < TM; i++)
                #pragma unroll
                for (int j = 0; j < TN; j++)
                    acc[i][j] = fmaf(a[i], b[j], acc[i][j]);
        }
        __syncthreads();

        if (have_next) {
            #pragma unroll
            for (int u = 0; u < LA; u++) {
                int idx = tid + u * THREADS;
                As[idx % BK][idx / BK] = ra[u];
            }
            #pragma unroll
            for (int u = 0; u < LB; u++) {
                int idx = tid + u * THREADS;
                Bs[idx % BK][idx / BK] = rb[u];
            }
            __syncthreads();
        }
    }

    // epilogue
    #pragma unroll
    for (int i = 0; i < TM; i++) {
        const int m = m0 + ty * TM + i;
        #pragma unroll
        for (int j = 0; j < TN; j++) {
            const int n = n0 + tx * TN + j;
            float v = acc[i][j];
            if (bias) v += bias[n];
            if (do_relu) v = fmaxf(v, 0.f);
            C[(long)m * ldc + n] = v;
        }
    }
}

// ---------------- s = rowsum(h), stored transposed st[k][b] ------------------
__global__ void rowsum_kernel(const float* __restrict__ h, float* __restrict__ st)
{
    const int gwarp = (blockIdx.x * blockDim.x + threadIdx.x) >> 5;
    const int lane = threadIdx.x & 31;
    if (gwarp >= B_ * S_) return;
    const float* row = h + (long)gwarp * E_;
    float v = 0.f;
    #pragma unroll
    for (int i = 0; i < E_ / 32; i++) v += row[lane + i * 32];
    #pragma unroll
    for (int o = 16; o > 0; o >>= 1) v += __shfl_xor_sync(0xFFFFFFFFu, v, o);
    if (lane == 0) {
        const int b = gwarp >> 7;      // / S_
        const int k = gwarp & (S_ - 1);
        st[k * B_ + b] = v;
    }
}

// ---------------- Weff[b,e,j] = sum_k w_red[e, k*E+j] * s[b,k] ---------------
// one block per e (256 threads = one j each); s held in smem as float4[k][b/4]
__global__ void weff_kernel(const float* __restrict__ w_red,
                            const float* __restrict__ st,
                            float* __restrict__ weff)
{
    __shared__ float4 s_sm[S_ * (B_ / 4)];   // [k][b4]  16KB
    const int e = blockIdx.x;
    const int j = threadIdx.x;

    for (int idx = threadIdx.x; idx < S_ * B_; idx += blockDim.x)
        ((float*)s_sm)[idx] = st[idx];
    __syncthreads();

    float acc[B_];
    #pragma unroll
    for (int b = 0; b < B_; b++) acc[b] = 0.f;

    const float* wp = w_red + (long)e * (S_ * E_) + j;
    #pragma unroll 4
    for (int k = 0; k < S_; k++) {
        const float w = wp[k * E_];
        #pragma unroll
        for (int bb = 0; bb < B_ / 4; bb++) {
            const float4 sv = s_sm[k * (B_ / 4) + bb];
            acc[bb * 4 + 0] = fmaf(w, sv.x, acc[bb * 4 + 0]);
            acc[bb * 4 + 1] = fmaf(w, sv.y, acc[bb * 4 + 1]);
            acc[bb * 4 + 2] = fmaf(w, sv.z, acc[bb * 4 + 2]);
            acc[bb * 4 + 3] = fmaf(w, sv.w, acc[bb * 4 + 3]);
        }
    }
    #pragma unroll
    for (int b = 0; b < B_; b++)
        weff[(long)b * (E_ * E_) + e * E_ + j] = acc[b];
}

// ---------------- y2 split-K reduce + bias + relu ----------------------------
__global__ void reduce5_kernel(const float* __restrict__ part,
                               const float* __restrict__ b_red2,
                               float* __restrict__ y2)
{
    const int idx = blockIdx.x * blockDim.x + threadIdx.x;   // [0, B_*E_)
    float v = 0.f;
    #pragma unroll 8
    for (int z = 0; z < 128; z++) v += part[z * (B_ * E_) + idx];
    v += b_red2[idx & (E_ - 1)];
    y2[idx] = fmaxf(v, 0.f);
}

// ---------------- launch -----------------------------------------------------
extern "C" void kernel_launch(void* const* d_in, const int* in_sizes, int n_in,
                              void* d_out, int out_size)
{
    const float* x      = (const float*)d_in[0];   // [B,S,V]
    const float* w_emb  = (const float*)d_in[1];   // [E,V]
    const float* b_emb  = (const float*)d_in[2];   // [E]
    const float* w_red  = (const float*)d_in[3];   // [E, S*E]
    const float* b_red  = (const float*)d_in[4];   // [E]
    const float* w_red2 = (const float*)d_in[5];   // [E, S*E]
    const float* b_red2 = (const float*)d_in[6];   // [E]
    const float* w_out  = (const float*)d_in[7];   // [V,E]
    const float* b_out  = (const float*)d_in[8];   // [V]
    float* out = (float*)d_out;                    // [B,V]

    float *h_p, *st_p, *weff_p, *y_p, *part_p, *y2_p;
    cudaGetSymbolAddress((void**)&h_p,    g_h);
    cudaGetSymbolAddress((void**)&st_p,   g_st);
    cudaGetSymbolAddress((void**)&weff_p, g_weff);
    cudaGetSymbolAddress((void**)&y_p,    g_y);
    cudaGetSymbolAddress((void**)&part_p, g_part);
    cudaGetSymbolAddress((void**)&y2_p,   g_y2);

    // Stage 1: h = relu(x @ w_emb^T + b_emb)   M=4096 N=256 K=8192
    gemm_nt_kernel<128, 64, 16, 8, 4><<<dim3(32, 4, 1), 256>>>(
        x, V_, 0, w_emb, V_, 0, h_p, E_, 0, b_emb, V_, 1);

    // Stage 2: s (transposed)
    rowsum_kernel<<<(B_ * S_ * 32) / 256, 256>>>(h_p, st_p);

    // Stage 3: Weff
    weff_kernel<<<E_, 256>>>(w_red, st_p, weff_p);

    // Stage 4: y = relu(batched h_b @ Weff_b^T + b_red)  per b: M=128 N=256 K=256
    gemm_nt_kernel<128, 64, 16, 8, 4><<<dim3(1, 4, B_), 256>>>(
        h_p, E_, (long)S_ * E_,
        weff_p, E_, (long)E_ * E_,
        y_p, E_, (long)S_ * E_,
        b_red, E_, 1);

    // Stage 5a: y2 partials, split-K over K=32768 into 128 chunks of 256
    gemm_nt_kernel<32, 64, 16, 2, 4><<<dim3(1, 4, 128), 256>>>(
        y_p, S_ * E_, 256,
        w_red2, S_ * E_, 256,
        part_p, E_, (long)B_ * E_,
        nullptr, 256, 0);

    // Stage 5b: reduce + bias + relu
    reduce5_kernel<<<(B_ * E_) / 256, 256>>>(part_p, b_red2, y2_p);

    // Stage 6: out = y2 @ w_out^T + b_out   M=32 N=8192 K=256
    gemm_nt_kernel<32, 64, 16, 2, 4><<<dim3(1, V_ / 64, 1), 256>>>(
        y2_p, E_, 0, w_out, E_, 0, out, V_, 0, b_out, E_, 0);
}

// round 3
// speedup vs baseline: 2.1711x; 2.1711x over previous
#include <cuda_runtime.h>
#include <cuda_bf16.h>
#include <cstdint>

// Problem: CrossBaby_1  (B=32, S=128, V=8192, E=256)
//   h    = relu(x @ w_emb^T + b_emb)                 [B*S, E]   <- mma.sync split-bf16
//   s    = sum_e h                                    [B, S]    <- fused into reduce1
//   Weff[b,e,j] = sum_k w_red[e, k*E+j] * s[b,k]      [B, E, E]
//   y    = relu(batched h_b @ Weff_b^T + b_red)       [B, S, E]
//   y2   = relu(y.flat @ w_red2^T + b_red2)           [B, E]
//   out  = y2 @ w_out^T + b_out                       [B, V]
//
// NOTE: harness ptxas target is sm_100 (no 'a') -> tcgen05/wgmma unavailable.
// Tensor path = mma.sync.m16n8k16 bf16 (HMMA), sm_80+ PTX.

#define B_  32
#define S_  128
#define V_  8192
#define E_  256
#define M1_ (B_ * S_)          // 4096 rows of stage-1 GEMM
#define SPLITK 2

// ---------------- scratch (static device globals; no allocation) ------------
__device__ __align__(128) __nv_bfloat16 g_xh[M1_ * V_];      // 64 MiB
__device__ __align__(128) __nv_bfloat16 g_xl[M1_ * V_];      // 64 MiB
__device__ __align__(128) __nv_bfloat16 g_wh[E_ * V_];       // 4 MiB
__device__ __align__(128) __nv_bfloat16 g_wl[E_ * V_];       // 4 MiB
__device__ __align__(128) float g_part1[SPLITK * M1_ * E_];  // 8 MiB
__device__ float g_h   [M1_ * E_];
__device__ float g_st  [S_ * B_];             // s transposed: [k][b]
__device__ float g_weff[B_ * E_ * E_];
__device__ float g_y   [M1_ * E_];
__device__ float g_part[128 * B_ * E_];
__device__ float g_y2  [B_ * E_];

// ---------------- PTX helpers ------------------------------------------------
__device__ __forceinline__ uint32_t smem_u32(const void* p) {
    uint32_t a;
    asm("{ .reg .u64 t; cvta.to.shared.u64 t, %1; cvt.u32.u64 %0, t; }" : "=r"(a) : "l"(p));
    return a;
}
__device__ __forceinline__ void cp16(uint32_t dst, const void* src) {
    asm volatile("cp.async.cg.shared.global [%0], [%1], 16;" :: "r"(dst), "l"(src) : "memory");
}
#define CP_COMMIT() asm volatile("cp.async.commit_group;" ::: "memory")
#define CP_WAIT(n)  asm volatile("cp.async.wait_group %0;" :: "n"(n) : "memory")

__device__ __forceinline__ void ldsm4(uint32_t* r, uint32_t addr) {
    asm volatile("ldmatrix.sync.aligned.m8n8.x4.shared.b16 {%0,%1,%2,%3}, [%4];"
        : "=r"(r[0]), "=r"(r[1]), "=r"(r[2]), "=r"(r[3]) : "r"(addr));
}
__device__ __forceinline__ void mma16816(float* d, const uint32_t* a, uint32_t b0, uint32_t b1) {
    asm volatile("mma.sync.aligned.m16n8k16.row.col.f32.bf16.bf16.f32 "
        "{%0,%1,%2,%3}, {%4,%5,%6,%7}, {%8,%9}, {%0,%1,%2,%3};"
        : "+f"(d[0]), "+f"(d[1]), "+f"(d[2]), "+f"(d[3])
        : "r"(a[0]), "r"(a[1]), "r"(a[2]), "r"(a[3]), "r"(b0), "r"(b1));
}

#define SW128(o) ((o) ^ (((o) >> 3) & 0x70))

// ============================================================================
// Stage-1 HMMA GEMM: part1[z][m][n] = sum_{k in z-span} x[m,k]*w_emb[n,k]
//   split-bf16 3-pass: AhBh + AlBh + AhBl, fp32 acc in registers.
//   CTA tile 128x128, BK=64, 8 warps (warp tile 32x64). grid (32, 2, SPLITK).
// ============================================================================
#define TK_     64
#define KSPAN   (V_ / SPLITK)       // 4096
#define NT_     (KSPAN / TK_)       // 64
#define AH_O    0
#define AL_O    16384
#define BH_O    32768
#define BL_O    49152
#define STG_SZ  65536
#define SMEM_TOT (2 * STG_SZ)       // 131072

__global__ void __launch_bounds__(256, 1) gemm1_hmma_kernel(
    const __nv_bfloat16* __restrict__ xh, const __nv_bfloat16* __restrict__ xl,
    const __nv_bfloat16* __restrict__ wh, const __nv_bfloat16* __restrict__ wl,
    float* __restrict__ part1)
{
    extern __shared__ char smem[];
    const uint32_t sb = smem_u32(smem);
    const int tid = threadIdx.x;
    const int wid = tid >> 5;
    const int lane = tid & 31;

    const int m0 = blockIdx.x * 128;
    const int n0 = blockIdx.y * 128;
    const int z  = blockIdx.z;
    const int kbase = z * KSPAN;

    const int warp_m = wid & 3;          // 4 warps along m (32 rows each)
    const int warp_n = wid >> 2;         // 2 warps along n (64 cols each)

    float acc[2][8][4];
    #pragma unroll
    for (int mt = 0; mt < 2; mt++)
        #pragma unroll
        for (int q = 0; q < 8; q++)
            #pragma unroll
            for (int r = 0; r < 4; r++) acc[mt][q][r] = 0.f;

    // ---- producer: each thread handles 4 16B-chunks of A and of B (h+l) ----
    auto issue_stage = [&](int s, int k0) {
        const uint32_t stg = sb + s * STG_SZ;
        #pragma unroll
        for (int i = 0; i < 4; i++) {
            const int c = tid + i * 256;          // 0..1023
            const int row = c >> 3, ch = c & 7;
            const uint32_t off = SW128((uint32_t)(row * 128 + ch * 16));
            const size_t ga = (size_t)(m0 + row) * V_ + k0 + ch * 8;
            cp16(stg + AH_O + off, xh + ga);
            cp16(stg + AL_O + off, xl + ga);
            const size_t gb = (size_t)(n0 + row) * V_ + k0 + ch * 8;
            cp16(stg + BH_O + off, wh + gb);
            cp16(stg + BL_O + off, wl + gb);
        }
    };

    // ldmatrix lane address components
    const int rowsel = lane & 15;        // row within 16-row tile
    const int khalf  = lane >> 4;        // 0/1 -> +8 k elements (16B)

    issue_stage(0, kbase);
    CP_COMMIT();

    for (int t = 0; t < NT_; t++) {
        if (t + 1 < NT_) {
            issue_stage((t + 1) & 1, kbase + (t + 1) * TK_);
            CP_COMMIT();
            CP_WAIT(1);
        } else {
            CP_WAIT(0);
        }
        __syncthreads();

        const uint32_t stg = sb + (t & 1) * STG_SZ;
        #pragma unroll
        for (int k16 = 0; k16 < 4; k16++) {
            const uint32_t kb = (uint32_t)(k16 * 32 + khalf * 16);
            uint32_t ah[2][4], al[2][4], bh[4][4], bl[4][4];
            #pragma unroll
            for (int mt = 0; mt < 2; mt++) {
                const uint32_t ro = (uint32_t)((warp_m * 32 + mt * 16 + rowsel) * 128) + kb;
                const uint32_t sw = SW128(ro);
                ldsm4(ah[mt], stg + AH_O + sw);
                ldsm4(al[mt], stg + AL_O + sw);
            }
            #pragma unroll
            for (int nt = 0; nt < 4; nt++) {
                const uint32_t ro = (uint32_t)((warp_n * 64 + nt * 16 + rowsel) * 128) + kb;
                const uint32_t sw = SW128(ro);
                ldsm4(bh[nt], stg + BH_O + sw);
                ldsm4(bl[nt], stg + BL_O + sw);
            }
            #pragma unroll
            for (int mt = 0; mt < 2; mt++) {
                #pragma unroll
                for (int q = 0; q < 8; q++) {
                    const int nt = q >> 1, w = q & 1;
                    const uint32_t bh0 = bh[nt][w], bh1 = bh[nt][w + 2];
                    const uint32_t bl0 = bl[nt][w], bl1 = bl[nt][w + 2];
                    mma16816(acc[mt][q], ah[mt], bh0, bh1);
                    mma16816(acc[mt][q], al[mt], bh0, bh1);
                    mma16816(acc[mt][q], ah[mt], bl0, bl1);
                }
            }
        }
        __syncthreads();
    }

    // ---- epilogue: write partials (no bias; reduce1 finishes) ----
    const int gid = lane >> 2;           // 0..7
    const int tig = lane & 3;            // 0..3
    float* base = part1 + (size_t)z * (M1_ * E_);
    #pragma unroll
    for (int mt = 0; mt < 2; mt++) {
        const int row0 = m0 + warp_m * 32 + mt * 16 + gid;
        #pragma unroll
        for (int q = 0; q < 8; q++) {
            const int col = n0 + warp_n * 64 + q * 8 + tig * 2;
            *(float2*)(base + (size_t)row0 * E_ + col) =
                make_float2(acc[mt][q][0], acc[mt][q][1]);
            *(float2*)(base + (size_t)(row0 + 8) * E_ + col) =
                make_float2(acc[mt][q][2], acc[mt][q][3]);
        }
    }
}

// ---------------- split fp32 -> bf16 hi/lo -----------------------------------
__global__ void split_bf16_kernel(const float* __restrict__ in,
                                  __nv_bfloat16* __restrict__ hi,
                                  __nv_bfloat16* __restrict__ lo, int n8)
{
    int i = blockIdx.x * blockDim.x + threadIdx.x;
    if (i >= n8) return;
    const float4* p = (const float4*)in;
    float4 a = p[2 * i], b = p[2 * i + 1];
    float v[8] = {a.x, a.y, a.z, a.w, b.x, b.y, b.z, b.w};
    union { __nv_bfloat16 e[8]; uint4 u; } H, L;
    #pragma unroll
    for (int q = 0; q < 8; q++) {
        __nv_bfloat16 h16 = __float2bfloat16(v[q]);
        H.e[q] = h16;
        L.e[q] = __float2bfloat16(v[q] - __bfloat162float(h16));
    }
    ((uint4*)hi)[i] = H.u;
    ((uint4*)lo)[i] = L.u;
}

// ---------------- split-K reduce + bias + relu + rowsum ----------------------
__global__ void reduce1_kernel(const float* __restrict__ part,
                               const float* __restrict__ b_emb,
                               float* __restrict__ h, float* __restrict__ st)
{
    const int warp = (blockIdx.x * blockDim.x + threadIdx.x) >> 5;   // row 0..4095
    const int lane = threadIdx.x & 31;
    const size_t CH = (size_t)M1_ * E_;
    const float* p0 = part + (size_t)warp * E_;
    float sum = 0.f;
    #pragma unroll
    for (int i = 0; i < 8; i++) {
        const int col = lane + i * 32;
        float v = p0[col] + p0[CH + col] + b_emb[col];
        v = fmaxf(v, 0.f);
        h[(size_t)warp * E_ + col] = v;
        sum += v;
    }
    #pragma unroll
    for (int o = 16; o > 0; o >>= 1) sum += __shfl_xor_sync(0xFFFFFFFFu, sum, o);
    if (lane == 0) {
        const int b = warp >> 7;
        const int k = warp & (S_ - 1);
        st[k * B_ + b] = sum;
    }
}

// ---------------- generic fp32 NT GEMM (stages 4, 5a, 6) ---------------------
template<int BM, int BN, int BK, int TM, int TN>
__global__ void gemm_nt_kernel(const float* __restrict__ A, int lda, long sAz,
                               const float* __restrict__ B, int ldb, long sBz,
                               float* __restrict__ C, int ldc, long sCz,
                               const float* __restrict__ bias,
                               int K, int do_relu)
{
    constexpr int THREADS = (BM * BN) / (TM * TN);
    constexpr int LA = (BM * BK) / THREADS;
    constexpr int LB = (BN * BK) / THREADS;
    constexpr int TX = BN / TN;

    __shared__ float As[BK][BM + 4];
    __shared__ float Bs[BK][BN + 4];

    const long z = blockIdx.z;
    A += z * sAz;  B += z * sBz;  C += z * sCz;

    const int m0 = blockIdx.x * BM;
    const int n0 = blockIdx.y * BN;
    const int tid = threadIdx.x;
    const int tx = tid % TX;
    const int ty = tid / TX;

    float acc[TM][TN];
    #pragma unroll
    for (int i = 0; i < TM; i++)
        #pragma unroll
        for (int j = 0; j < TN; j++) acc[i][j] = 0.f;

    float ra[LA], rb[LB];
    const int nTiles = K / BK;

    #pragma unroll
    for (int u = 0; u < LA; u++) {
        int idx = tid + u * THREADS;
        ra[u] = A[(long)(m0 + idx / BK) * lda + (idx % BK)];
    }
    #pragma unroll
    for (int u = 0; u < LB; u++) {
        int idx = tid + u * THREADS;
        rb[u] = B[(long)(n0 + idx / BK) * ldb + (idx % BK)];
    }
    #pragma unroll
    for (int u = 0; u < LA; u++) {
        int idx = tid + u * THREADS;
        As[idx % BK][idx / BK] = ra[u];
    }
    #pragma unroll
    for (int u = 0; u < LB; u++) {
        int idx = tid + u * THREADS;
        Bs[idx % BK][idx / BK] = rb[u];
    }
    __syncthreads();

    for (int t = 0; t < nTiles; t++) {
        const int k_next = (t + 1) * BK;
        const bool have_next = (t + 1) < nTiles;
        if (have_next) {
            #pragma unroll
            for (int u = 0; u < LA; u++) {
                int idx = tid + u * THREADS;
                ra[u] = A[(long)(m0 + idx / BK) * lda + k_next + (idx % BK)];
            }
            #pragma unroll
            for (int u = 0; u < LB; u++) {
                int idx = tid + u * THREADS;
                rb[u] = B[(long)(n0 + idx / BK) * ldb + k_next + (idx % BK)];
            }
        }

        #pragma unroll
        for (int kk = 0; kk < BK; kk++) {
            float a[TM], b[TN];
            #pragma unroll
            for (int i = 0; i < TM; i++) a[i] = As[kk][ty * TM + i];
            #pragma unroll
            for (int j = 0; j < TN; j++) b[j] = Bs[kk][tx * TN + j];
            #pragma unroll
            for (int i = 0; i < TM; i++)
                #pragma unroll
                for (int j = 0; j < TN; j++)
                    acc[i][j] = fmaf(a[i], b[j], acc[i][j]);
        }
        __syncthreads();

        if (have_next) {
            #pragma unroll
            for (int u = 0; u < LA; u++) {
                int idx = tid + u * THREADS;
                As[idx % BK][idx / BK] = ra[u];
            }
            #pragma unroll
            for (int u = 0; u < LB; u++) {
                int idx = tid + u * THREADS;
                Bs[idx % BK][idx / BK] = rb[u];
            }
            __syncthreads();
        }
    }

    #pragma unroll
    for (int i = 0; i < TM; i++) {
        const int m = m0 + ty * TM + i;
        #pragma unroll
        for (int j = 0; j < TN; j++) {
            const int n = n0 + tx * TN + j;
            float v = acc[i][j];
            if (bias) v += bias[n];
            if (do_relu) v = fmaxf(v, 0.f);
            C[(long)m * ldc + n] = v;
        }
    }
}

// ---------------- Weff[b,e,j] = sum_k w_red[e, k*E+j] * s[b,k] ---------------
__global__ void weff_kernel(const float* __restrict__ w_red,
                            const float* __restrict__ st,
                            float* __restrict__ weff)
{
    __shared__ float4 s_sm[S_ * (B_ / 4)];
    const int e = blockIdx.x;
    const int j = threadIdx.x;

    for (int idx = threadIdx.x; idx < S_ * B_; idx += blockDim.x)
        ((float*)s_sm)[idx] = st[idx];
    __syncthreads();

    float acc[B_];
    #pragma unroll
    for (int b = 0; b < B_; b++) acc[b] = 0.f;

    const float* wp = w_red + (long)e * (S_ * E_) + j;
    #pragma unroll 4
    for (int k = 0; k < S_; k++) {
        const float w = wp[k * E_];
        #pragma unroll
        for (int bb = 0; bb < B_ / 4; bb++) {
            const float4 sv = s_sm[k * (B_ / 4) + bb];
            acc[bb * 4 + 0] = fmaf(w, sv.x, acc[bb * 4 + 0]);
            acc[bb * 4 + 1] = fmaf(w, sv.y, acc[bb * 4 + 1]);
            acc[bb * 4 + 2] = fmaf(w, sv.z, acc[bb * 4 + 2]);
            acc[bb * 4 + 3] = fmaf(w, sv.w, acc[bb * 4 + 3]);
        }
    }
    #pragma unroll
    for (int b = 0; b < B_; b++)
        weff[(long)b * (E_ * E_) + e * E_ + j] = acc[b];
}

// ---------------- y2 split-K reduce + bias + relu ----------------------------
__global__ void reduce5_kernel(const float* __restrict__ part,
                               const float* __restrict__ b_red2,
                               float* __restrict__ y2)
{
    const int idx = blockIdx.x * blockDim.x + threadIdx.x;
    float v = 0.f;
    #pragma unroll 8
    for (int z = 0; z < 128; z++) v += part[z * (B_ * E_) + idx];
    v += b_red2[idx & (E_ - 1)];
    y2[idx] = fmaxf(v, 0.f);
}

// ---------------- launch -----------------------------------------------------
extern "C" void kernel_launch(void* const* d_in, const int* in_sizes, int n_in,
                              void* d_out, int out_size)
{
    const float* x      = (const float*)d_in[0];
    const float* w_emb  = (const float*)d_in[1];
    const float* b_emb  = (const float*)d_in[2];
    const float* w_red  = (const float*)d_in[3];
    const float* b_red  = (const float*)d_in[4];
    const float* w_red2 = (const float*)d_in[5];
    const float* b_red2 = (const float*)d_in[6];
    const float* w_out  = (const float*)d_in[7];
    const float* b_out  = (const float*)d_in[8];
    float* out = (float*)d_out;

    __nv_bfloat16 *xh_p, *xl_p, *wh_p, *wl_p;
    float *part1_p, *h_p, *st_p, *weff_p, *y_p, *part_p, *y2_p;
    cudaGetSymbolAddress((void**)&xh_p,    g_xh);
    cudaGetSymbolAddress((void**)&xl_p,    g_xl);
    cudaGetSymbolAddress((void**)&wh_p,    g_wh);
    cudaGetSymbolAddress((void**)&wl_p,    g_wl);
    cudaGetSymbolAddress((void**)&part1_p, g_part1);
    cudaGetSymbolAddress((void**)&h_p,     g_h);
    cudaGetSymbolAddress((void**)&st_p,    g_st);
    cudaGetSymbolAddress((void**)&weff_p,  g_weff);
    cudaGetSymbolAddress((void**)&y_p,     g_y);
    cudaGetSymbolAddress((void**)&part_p,  g_part);
    cudaGetSymbolAddress((void**)&y2_p,    g_y2);

    cudaFuncSetAttribute(gemm1_hmma_kernel,
                         cudaFuncAttributeMaxDynamicSharedMemorySize, SMEM_TOT);

    // Stage 1a: split x and w_emb into bf16 hi/lo
    split_bf16_kernel<<<(M1_ * V_ / 8 + 255) / 256, 256>>>(x, xh_p, xl_p, M1_ * V_ / 8);
    split_bf16_kernel<<<(E_ * V_ / 8 + 255) / 256, 256>>>(w_emb, wh_p, wl_p, E_ * V_ / 8);

    // Stage 1b: HMMA split-bf16 GEMM -> split-K partials
    gemm1_hmma_kernel<<<dim3(M1_ / 128, E_ / 128, SPLITK), 256, SMEM_TOT>>>(
        xh_p, xl_p, wh_p, wl_p, part1_p);

    // Stage 1c/2: reduce partials + bias + relu -> h ; rowsum -> st
    reduce1_kernel<<<M1_ / 8, 256>>>(part1_p, b_emb, h_p, st_p);

    // Stage 3: Weff
    weff_kernel<<<E_, 256>>>(w_red, st_p, weff_p);

    // Stage 4: y = relu(batched h_b @ Weff_b^T + b_red)
    gemm_nt_kernel<128, 64, 16, 8, 4><<<dim3(1, 4, B_), 256>>>(
        h_p, E_, (long)S_ * E_,
        weff_p, E_, (long)E_ * E_,
        y_p, E_, (long)S_ * E_,
        b_red, E_, 1);

    // Stage 5a: y2 partials, split-K over K=32768 into 128 chunks of 256
    gemm_nt_kernel<32, 64, 16, 2, 4><<<dim3(1, 4, 128), 256>>>(
        y_p, S_ * E_, 256,
        w_red2, S_ * E_, 256,
        part_p, E_, (long)B_ * E_,
        nullptr, 256, 0);

    // Stage 5b: reduce + bias + relu
    reduce5_kernel<<<(B_ * E_) / 256, 256>>>(part_p, b_red2, y2_p);

    // Stage 6: out = y2 @ w_out^T + b_out
    gemm_nt_kernel<32, 64, 16, 2, 4><<<dim3(1, V_ / 64, 1), 256>>>(
        y2_p, E_, 0, w_out, E_, 0, out, V_, 0, b_out, E_, 0);
}

// round 4
// speedup vs baseline: 2.4575x; 1.1320x over previous
#include <cuda_runtime.h>
#include <cuda_fp16.h>
#include <cuda_bf16.h>
#include <cstdint>

// Problem: CrossBaby_1  (B=32, S=128, V=8192, E=256)
//   h    = relu(x @ w_emb^T + b_emb)                 [B*S, E]   <- HMMA fp16 2-pass
//   s    = sum_e h                                    [B, S]    <- fused into reduce1
//   Weff[b,e,j] = sum_k w_red[e, k*E+j] * s[b,k]      [B, E, E]
//   y    = relu(batched h_b @ Weff_b^T + b_red)       [B, S, E]
//   y2   = relu(y.flat @ w_red2^T + b_red2)           [B, E]
//   out  = y2 @ w_out^T + b_out                       [B, V]
//
// Target is sm_100 (no 'a'): tcgen05 unavailable; tensor path = mma.sync HMMA.
// Stage-1 numeric scheme: x = xh + xl*2^-12 (fp16 h + scaled fp16 residual),
// w in plain fp16. D = (Ah*Bh) + 2^-12*(Al'*Bh), two accumulators.

#define B_  32
#define S_  128
#define V_  8192
#define E_  256
#define M1_ (B_ * S_)
#define SPLITK 2

// ---------------- scratch (static device globals; no allocation) ------------
__device__ __align__(128) __half g_wh[E_ * V_];              // 4 MiB fp16 weights
__device__ __align__(128) float g_part1[SPLITK * M1_ * E_];  // 8 MiB
__device__ float g_h   [M1_ * E_];
__device__ float g_st  [S_ * B_];             // s transposed: [k][b]
__device__ float g_weff[B_ * E_ * E_];
__device__ float g_y   [M1_ * E_];
__device__ float g_part[128 * B_ * E_];
__device__ float g_y2  [B_ * E_];

// ---------------- PTX helpers ------------------------------------------------
__device__ __forceinline__ uint32_t smem_u32(const void* p) {
    uint32_t a;
    asm("{ .reg .u64 t; cvta.to.shared.u64 t, %1; cvt.u32.u64 %0, t; }" : "=r"(a) : "l"(p));
    return a;
}
__device__ __forceinline__ void cp16(uint32_t dst, const void* src) {
    asm volatile("cp.async.cg.shared.global [%0], [%1], 16;" :: "r"(dst), "l"(src) : "memory");
}
#define CP_COMMIT() asm volatile("cp.async.commit_group;" ::: "memory")
#define CP_WAIT(n)  asm volatile("cp.async.wait_group %0;" :: "n"(n) : "memory")

__device__ __forceinline__ void ldsm4(uint32_t* r, uint32_t addr) {
    asm volatile("ldmatrix.sync.aligned.m8n8.x4.shared.b16 {%0,%1,%2,%3}, [%4];"
        : "=r"(r[0]), "=r"(r[1]), "=r"(r[2]), "=r"(r[3]) : "r"(addr));
}
__device__ __forceinline__ void mma16816h(float* d, const uint32_t* a, uint32_t b0, uint32_t b1) {
    asm volatile("mma.sync.aligned.m16n8k16.row.col.f32.f16.f16.f32 "
        "{%0,%1,%2,%3}, {%4,%5,%6,%7}, {%8,%9}, {%0,%1,%2,%3};"
        : "+f"(d[0]), "+f"(d[1]), "+f"(d[2]), "+f"(d[3])
        : "r"(a[0]), "r"(a[1]), "r"(a[2]), "r"(a[3]), "r"(b0), "r"(b1));
}
__device__ __forceinline__ void sts128(uint32_t addr, uint32_t a, uint32_t b, uint32_t c, uint32_t d) {
    asm volatile("st.shared.v4.b32 [%0], {%1,%2,%3,%4};" :: "r"(addr), "r"(a), "r"(b), "r"(c), "r"(d) : "memory");
}

#define SW128(o) ((o) ^ (((o) >> 3) & 0x70))

// ============================================================================
// Stage-1 HMMA GEMM (fused split): part1[z][m][n] = sum_k x[m,k]*w_emb[n,k]
//   CTA 128x128, BK=64, 8 warps (warp 32x64), grid (32 m, 2 n, SPLITK z).
//   A path: cp.async fp32 x -> smem -> convert to (Ah, Al*2^12) fp16 smem.
// ============================================================================
#define TK_     64
#define KSPAN   (V_ / SPLITK)       // 4096
#define NT_     (KSPAN / TK_)       // 64
#define AF_ROWB 272                 // fp32 A staging row stride (64*4 + 16 pad)
#define AF_O    0                   // 128*272 = 34816 B
#define STG0_O  36864
#define STG_SZ  49152               // Ah 16K + Al 16K + Bh 16K
#define AH_O    0
#define AL_O    16384
#define BH_O    32768
#define SMEM_TOT (STG0_O + 2 * STG_SZ)   // 135168 B

__global__ void __launch_bounds__(256, 1) gemm1_hmma_kernel(
    const float* __restrict__ x, const __half* __restrict__ wh,
    float* __restrict__ part1)
{
    extern __shared__ char smem[];
    const uint32_t sb = smem_u32(smem);
    const int tid = threadIdx.x;
    const int wid = tid >> 5;
    const int lane = tid & 31;

    const int m0 = blockIdx.x * 128;
    const int n0 = blockIdx.y * 128;
    const int z  = blockIdx.z;
    const int kbase = z * KSPAN;

    const int warp_m = wid & 3;          // 4 warps along m (32 rows each)
    const int warp_n = wid >> 2;         // 2 warps along n (64 cols each)

    float accm[2][8][4], accc[2][8][4];
    #pragma unroll
    for (int mt = 0; mt < 2; mt++)
        #pragma unroll
        for (int q = 0; q < 8; q++)
            #pragma unroll
            for (int r = 0; r < 4; r++) { accm[mt][q][r] = 0.f; accc[mt][q][r] = 0.f; }

    // ---- A fp32 staging: 128 rows x 64 fp32; 16 chunks of 16B per row ------
    auto issue_A = [&](int k0) {
        #pragma unroll
        for (int i = 0; i < 8; i++) {
            const int c = tid + i * 256;          // 0..2047
            const int row = c >> 4, ch = c & 15;  // 16 chunks/row
            cp16(sb + AF_O + row * AF_ROWB + ch * 16,
                 x + (size_t)(m0 + row) * V_ + k0 + ch * 4);
        }
    };
    // ---- B fp16: 128 rows x 64 fp16 (8 x 16B chunks per row) ---------------
    auto issue_B = [&](int s, int k0) {
        const uint32_t stg = sb + STG0_O + s * STG_SZ + BH_O;
        #pragma unroll
        for (int i = 0; i < 4; i++) {
            const int c = tid + i * 256;          // 0..1023
            const int row = c >> 3, ch = c & 7;
            cp16(stg + SW128((uint32_t)(row * 128 + ch * 16)),
                 wh + (size_t)(n0 + row) * V_ + k0 + ch * 8);
        }
    };
    // ---- convert fp32 A staging -> Ah / Al(*4096) fp16 smem ----------------
    auto convert_A = [&](int s) {
        const uint32_t stg = sb + STG0_O + s * STG_SZ;
        #pragma unroll
        for (int i = 0; i < 4; i++) {
            const int c = tid + i * 256;          // 0..1023
            const int row = c >> 3, ch = c & 7;
            const float4* src = (const float4*)(smem + AF_O + row * AF_ROWB + ch * 32);
            float4 u = src[0], v = src[1];
            float f[8] = {u.x, u.y, u.z, u.w, v.x, v.y, v.z, v.w};
            uint32_t hh[4], ll[4];
            #pragma unroll
            for (int p = 0; p < 4; p++) {
                __half h0 = __float2half_rn(f[2 * p]);
                __half h1 = __float2half_rn(f[2 * p + 1]);
                __half l0 = __float2half_rn((f[2 * p]     - __half2float(h0)) * 4096.f);
                __half l1 = __float2half_rn((f[2 * p + 1] - __half2float(h1)) * 4096.f);
                __half2 H = __halves2half2(h0, h1), L = __halves2half2(l0, l1);
                hh[p] = *(uint32_t*)&H;
                ll[p] = *(uint32_t*)&L;
            }
            const uint32_t off = SW128((uint32_t)(row * 128 + ch * 16));
            sts128(stg + AH_O + off, hh[0], hh[1], hh[2], hh[3]);
            sts128(stg + AL_O + off, ll[0], ll[1], ll[2], ll[3]);
        }
    };

    const int rowsel = lane & 15;
    const int khalf  = lane >> 4;

    issue_A(kbase);
    issue_B(0, kbase);
    CP_COMMIT();

    for (int t = 0; t < NT_; t++) {
        const int s = t & 1;
        CP_WAIT(0);
        __syncthreads();
        convert_A(s);
        __syncthreads();
        if (t + 1 < NT_) {
            issue_A(kbase + (t + 1) * TK_);
            issue_B(s ^ 1, kbase + (t + 1) * TK_);
            CP_COMMIT();
        }

        const uint32_t stg = sb + STG0_O + s * STG_SZ;
        #pragma unroll
        for (int k16 = 0; k16 < 4; k16++) {
            const uint32_t kb = (uint32_t)(k16 * 32 + khalf * 16);
            uint32_t ah[2][4], al[2][4], bh[4][4];
            #pragma unroll
            for (int mt = 0; mt < 2; mt++) {
                const uint32_t sw = SW128((uint32_t)((warp_m * 32 + mt * 16 + rowsel) * 128) + kb);
                ldsm4(ah[mt], stg + AH_O + sw);
                ldsm4(al[mt], stg + AL_O + sw);
            }
            #pragma unroll
            for (int nt = 0; nt < 4; nt++) {
                const uint32_t sw = SW128((uint32_t)((warp_n * 64 + nt * 16 + rowsel) * 128) + kb);
                ldsm4(bh[nt], stg + BH_O + sw);
            }
            #pragma unroll
            for (int mt = 0; mt < 2; mt++) {
                #pragma unroll
                for (int q = 0; q < 8; q++) {
                    const int nt = q >> 1, w = q & 1;
                    const uint32_t b0 = bh[nt][w], b1 = bh[nt][w + 2];
                    mma16816h(accm[mt][q], ah[mt], b0, b1);
                    mma16816h(accc[mt][q], al[mt], b0, b1);
                }
            }
        }
        __syncthreads();
    }

    // ---- epilogue: D = accm + accc/4096; write partials ----
    const int gid = lane >> 2;
    const int tig = lane & 3;
    const float inv = 1.f / 4096.f;
    float* base = part1 + (size_t)z * (M1_ * E_);
    #pragma unroll
    for (int mt = 0; mt < 2; mt++) {
        const int row0 = m0 + warp_m * 32 + mt * 16 + gid;
        #pragma unroll
        for (int q = 0; q < 8; q++) {
            const int col = n0 + warp_n * 64 + q * 8 + tig * 2;
            float d0 = fmaf(accc[mt][q][0], inv, accm[mt][q][0]);
            float d1 = fmaf(accc[mt][q][1], inv, accm[mt][q][1]);
            float d2 = fmaf(accc[mt][q][2], inv, accm[mt][q][2]);
            float d3 = fmaf(accc[mt][q][3], inv, accm[mt][q][3]);
            *(float2*)(base + (size_t)row0 * E_ + col)       = make_float2(d0, d1);
            *(float2*)(base + (size_t)(row0 + 8) * E_ + col) = make_float2(d2, d3);
        }
    }
}

// ---------------- convert w_emb fp32 -> fp16 ---------------------------------
__global__ void wconv_kernel(const float* __restrict__ in, __half* __restrict__ o, int n8)
{
    int i = blockIdx.x * blockDim.x + threadIdx.x;
    if (i >= n8) return;
    const float4* p = (const float4*)in;
    float4 a = p[2 * i], b = p[2 * i + 1];
    float v[8] = {a.x, a.y, a.z, a.w, b.x, b.y, b.z, b.w};
    union { __half e[8]; uint4 u; } H;
    #pragma unroll
    for (int q = 0; q < 8; q++) H.e[q] = __float2half_rn(v[q]);
    ((uint4*)o)[i] = H.u;
}

// ---------------- split-K reduce + bias + relu + rowsum ----------------------
__global__ void reduce1_kernel(const float* __restrict__ part,
                               const float* __restrict__ b_emb,
                               float* __restrict__ h, float* __restrict__ st)
{
    const int warp = (blockIdx.x * blockDim.x + threadIdx.x) >> 5;   // row 0..4095
    const int lane = threadIdx.x & 31;
    const size_t CH = (size_t)M1_ * E_;
    const float* p0 = part + (size_t)warp * E_;
    float sum = 0.f;
    #pragma unroll
    for (int i = 0; i < 8; i++) {
        const int col = lane + i * 32;
        float v = p0[col] + p0[CH + col] + b_emb[col];
        v = fmaxf(v, 0.f);
        h[(size_t)warp * E_ + col] = v;
        sum += v;
    }
    #pragma unroll
    for (int o = 16; o > 0; o >>= 1) sum += __shfl_xor_sync(0xFFFFFFFFu, sum, o);
    if (lane == 0) {
        const int b = warp >> 7;
        const int k = warp & (S_ - 1);
        st[k * B_ + b] = sum;
    }
}

// ---------------- generic fp32 NT GEMM (stages 4, 5a, 6) ---------------------
template<int BM, int BN, int BK, int TM, int TN>
__global__ void gemm_nt_kernel(const float* __restrict__ A, int lda, long sAz,
                               const float* __restrict__ B, int ldb, long sBz,
                               float* __restrict__ C, int ldc, long sCz,
                               const float* __restrict__ bias,
                               int K, int do_relu)
{
    constexpr int THREADS = (BM * BN) / (TM * TN);
    constexpr int LA = (BM * BK) / THREADS;
    constexpr int LB = (BN * BK) / THREADS;
    constexpr int TX = BN / TN;

    __shared__ float As[BK][BM + 4];
    __shared__ float Bs[BK][BN + 4];

    const long z = blockIdx.z;
    A += z * sAz;  B += z * sBz;  C += z * sCz;

    const int m0 = blockIdx.x * BM;
    const int n0 = blockIdx.y * BN;
    const int tid = threadIdx.x;
    const int tx = tid % TX;
    const int ty = tid / TX;

    float acc[TM][TN];
    #pragma unroll
    for (int i = 0; i < TM; i++)
        #pragma unroll
        for (int j = 0; j < TN; j++) acc[i][j] = 0.f;

    float ra[LA], rb[LB];
    const int nTiles = K / BK;

    #pragma unroll
    for (int u = 0; u < LA; u++) {
        int idx = tid + u * THREADS;
        ra[u] = A[(long)(m0 + idx / BK) * lda + (idx % BK)];
    }
    #pragma unroll
    for (int u = 0; u < LB; u++) {
        int idx = tid + u * THREADS;
        rb[u] = B[(long)(n0 + idx / BK) * ldb + (idx % BK)];
    }
    #pragma unroll
    for (int u = 0; u < LA; u++) {
        int idx = tid + u * THREADS;
        As[idx % BK][idx / BK] = ra[u];
    }
    #pragma unroll
    for (int u = 0; u < LB; u++) {
        int idx = tid + u * THREADS;
        Bs[idx % BK][idx / BK] = rb[u];
    }
    __syncthreads();

    for (int t = 0; t < nTiles; t++) {
        const int k_next = (t + 1) * BK;
        const bool have_next = (t + 1) < nTiles;
        if (have_next) {
            #pragma unroll
            for (int u = 0; u < LA; u++) {
                int idx = tid + u * THREADS;
                ra[u] = A[(long)(m0 + idx / BK) * lda + k_next + (idx % BK)];
            }
            #pragma unroll
            for (int u = 0; u < LB; u++) {
                int idx = tid + u * THREADS;
                rb[u] = B[(long)(n0 + idx / BK) * ldb + k_next + (idx % BK)];
            }
        }

        #pragma unroll
        for (int kk = 0; kk < BK; kk++) {
            float a[TM], b[TN];
            #pragma unroll
            for (int i = 0; i < TM; i++) a[i] = As[kk][ty * TM + i];
            #pragma unroll
            for (int j = 0; j < TN; j++) b[j] = Bs[kk][tx * TN + j];
            #pragma unroll
            for (int i = 0; i < TM; i++)
                #pragma unroll
                for (int j = 0; j < TN; j++)
                    acc[i][j] = fmaf(a[i], b[j], acc[i][j]);
        }
        __syncthreads();

        if (have_next) {
            #pragma unroll
            for (int u = 0; u < LA; u++) {
                int idx = tid + u * THREADS;
                As[idx % BK][idx / BK] = ra[u];
            }
            #pragma unroll
            for (int u = 0; u < LB; u++) {
                int idx = tid + u * THREADS;
                Bs[idx % BK][idx / BK] = rb[u];
            }
            __syncthreads();
        }
    }

    #pragma unroll
    for (int i = 0; i < TM; i++) {
        const int m = m0 + ty * TM + i;
        #pragma unroll
        for (int j = 0; j < TN; j++) {
            const int n = n0 + tx * TN + j;
            float v = acc[i][j];
            if (bias) v += bias[n];
            if (do_relu) v = fmaxf(v, 0.f);
            C[(long)m * ldc + n] = v;
        }
    }
}

// ---------------- Weff[b,e,j] = sum_k w_red[e, k*E+j] * s[b,k] ---------------
__global__ void weff_kernel(const float* __restrict__ w_red,
                            const float* __restrict__ st,
                            float* __restrict__ weff)
{
    __shared__ float4 s_sm[S_ * (B_ / 4)];
    const int e = blockIdx.x;
    const int j = threadIdx.x;

    for (int idx = threadIdx.x; idx < S_ * B_; idx += blockDim.x)
        ((float*)s_sm)[idx] = st[idx];
    __syncthreads();

    float acc[B_];
    #pragma unroll
    for (int b = 0; b < B_; b++) acc[b] = 0.f;

    const float* wp = w_red + (long)e * (S_ * E_) + j;
    #pragma unroll 4
    for (int k = 0; k < S_; k++) {
        const float w = wp[k * E_];
        #pragma unroll
        for (int bb = 0; bb < B_ / 4; bb++) {
            const float4 sv = s_sm[k * (B_ / 4) + bb];
            acc[bb * 4 + 0] = fmaf(w, sv.x, acc[bb * 4 + 0]);
            acc[bb * 4 + 1] = fmaf(w, sv.y, acc[bb * 4 + 1]);
            acc[bb * 4 + 2] = fmaf(w, sv.z, acc[bb * 4 + 2]);
            acc[bb * 4 + 3] = fmaf(w, sv.w, acc[bb * 4 + 3]);
        }
    }
    #pragma unroll
    for (int b = 0; b < B_; b++)
        weff[(long)b * (E_ * E_) + e * E_ + j] = acc[b];
}

// ---------------- y2 split-K reduce + bias + relu ----------------------------
__global__ void reduce5_kernel(const float* __restrict__ part,
                               const float* __restrict__ b_red2,
                               float* __restrict__ y2)
{
    const int idx = blockIdx.x * blockDim.x + threadIdx.x;
    float v = 0.f;
    #pragma unroll 8
    for (int z = 0; z < 128; z++) v += part[z * (B_ * E_) + idx];
    v += b_red2[idx & (E_ - 1)];
    y2[idx] = fmaxf(v, 0.f);
}

// ---------------- launch -----------------------------------------------------
extern "C" void kernel_launch(void* const* d_in, const int* in_sizes, int n_in,
                              void* d_out, int out_size)
{
    const float* x      = (const float*)d_in[0];
    const float* w_emb  = (const float*)d_in[1];
    const float* b_emb  = (const float*)d_in[2];
    const float* w_red  = (const float*)d_in[3];
    const float* b_red  = (const float*)d_in[4];
    const float* w_red2 = (const float*)d_in[5];
    const float* b_red2 = (const float*)d_in[6];
    const float* w_out  = (const float*)d_in[7];
    const float* b_out  = (const float*)d_in[8];
    float* out = (float*)d_out;

    __half *wh_p;
    float *part1_p, *h_p, *st_p, *weff_p, *y_p, *part_p, *y2_p;
    cudaGetSymbolAddress((void**)&wh_p,    g_wh);
    cudaGetSymbolAddress((void**)&part1_p, g_part1);
    cudaGetSymbolAddress((void**)&h_p,     g_h);
    cudaGetSymbolAddress((void**)&st_p,    g_st);
    cudaGetSymbolAddress((void**)&weff_p,  g_weff);
    cudaGetSymbolAddress((void**)&y_p,     g_y);
    cudaGetSymbolAddress((void**)&part_p,  g_part);
    cudaGetSymbolAddress((void**)&y2_p,    g_y2);

    cudaFuncSetAttribute(gemm1_hmma_kernel,
                         cudaFuncAttributeMaxDynamicSharedMemorySize, SMEM_TOT);

    // Stage 1a: w_emb -> fp16
    wconv_kernel<<<(E_ * V_ / 8 + 255) / 256, 256>>>(w_emb, wh_p, E_ * V_ / 8);

    // Stage 1b: HMMA fp16 2-pass GEMM (fused x split) -> split-K partials
    gemm1_hmma_kernel<<<dim3(M1_ / 128, E_ / 128, SPLITK), 256, SMEM_TOT>>>(
        x, wh_p, part1_p);

    // Stage 1c/2: reduce partials + bias + relu -> h ; rowsum -> st
    reduce1_kernel<<<M1_ / 8, 256>>>(part1_p, b_emb, h_p, st_p);

    // Stage 3: Weff
    weff_kernel<<<E_, 256>>>(w_red, st_p, weff_p);

    // Stage 4: y = relu(batched h_b @ Weff_b^T + b_red)
    gemm_nt_kernel<128, 64, 16, 8, 4><<<dim3(1, 4, B_), 256>>>(
        h_p, E_, (long)S_ * E_,
        weff_p, E_, (long)E_ * E_,
        y_p, E_, (long)S_ * E_,
        b_red, E_, 1);

    // Stage 5a: y2 partials, split-K over K=32768 into 128 chunks of 256
    gemm_nt_kernel<32, 64, 16, 2, 4><<<dim3(1, 4, 128), 256>>>(
        y_p, S_ * E_, 256,
        w_red2, S_ * E_, 256,
        part_p, E_, (long)B_ * E_,
        nullptr, 256, 0);

    // Stage 5b: reduce + bias + relu
    reduce5_kernel<<<(B_ * E_) / 256, 256>>>(part_p, b_red2, y2_p);

    // Stage 6: out = y2 @ w_out^T + b_out
    gemm_nt_kernel<32, 64, 16, 2, 4><<<dim3(1, V_ / 64, 1), 256>>>(
        y2_p, E_, 0, w_out, E_, 0, out, V_, 0, b_out, E_, 0);
}

// round 6
// speedup vs baseline: 2.7731x; 1.1284x over previous
#include <cuda_runtime.h>
#include <cuda_fp16.h>
#include <cuda_bf16.h>
#include <cstdint>

// Problem: CrossBaby_1  (B=32, S=128, V=8192, E=256)
//   h    = relu(x @ w_emb^T + b_emb)                 [B*S, E]   <- HMMA fp16 2-pass
//   s    = sum_e h                                    [B, S]    <- fused into reduce1
//   Weff[b,e,j] = sum_k w_red[e, k*E+j] * s[b,k]      [B, E, E]
//   y    = relu(batched h_b @ Weff_b^T + b_red)       [B, S, E]
//   y2   = relu(y.flat @ w_red2^T + b_red2)           [B, E]
//   out  = y2 @ w_out^T + b_out                       [B, V]
//
// Target sm_100 (no 'a'): tensor path = mma.sync HMMA fp16.
// Stage-1: x = xh + xl*2^-12 (fp16 + scaled fp16 residual, split IN REGISTERS),
// w in fp16. D = Ah*Bh + 2^-12*(Al'*Bh), two fp32 accumulator sets.

#define B_  32
#define S_  128
#define V_  8192
#define E_  256
#define M1_ (B_ * S_)
#define SPLITK 2

// ---------------- scratch (static device globals; no allocation) ------------
__device__ __align__(128) __half g_wh[E_ * V_];              // 4 MiB fp16 weights
__device__ __align__(128) float g_part1[SPLITK * M1_ * E_];  // 8 MiB
__device__ float g_h   [M1_ * E_];
__device__ float g_st  [S_ * B_];             // s transposed: [k][b]
__device__ float g_weff[B_ * E_ * E_];
__device__ float g_y   [M1_ * E_];
__device__ float g_part[128 * B_ * E_];
__device__ float g_y2  [B_ * E_];

// ---------------- PTX helpers ------------------------------------------------
__device__ __forceinline__ uint32_t smem_u32(const void* p) {
    uint32_t a;
    asm("{ .reg .u64 t; cvta.to.shared.u64 t, %1; cvt.u32.u64 %0, t; }" : "=r"(a) : "l"(p));
    return a;
}
__device__ __forceinline__ void cp16(uint32_t dst, const void* src) {
    asm volatile("cp.async.cg.shared.global [%0], [%1], 16;" :: "r"(dst), "l"(src) : "memory");
}
#define CP_COMMIT() asm volatile("cp.async.commit_group;" ::: "memory")
#define CP_WAIT(n)  asm volatile("cp.async.wait_group %0;" :: "n"(n) : "memory")

__device__ __forceinline__ void ldsm4(uint32_t* r, uint32_t addr) {
    asm volatile("ldmatrix.sync.aligned.m8n8.x4.shared.b16 {%0,%1,%2,%3}, [%4];"
        : "=r"(r[0]), "=r"(r[1]), "=r"(r[2]), "=r"(r[3]) : "r"(addr));
}
__device__ __forceinline__ void mma16816h(float* d, const uint32_t* a, uint32_t b0, uint32_t b1) {
    asm volatile("mma.sync.aligned.m16n8k16.row.col.f32.f16.f16.f32 "
        "{%0,%1,%2,%3}, {%4,%5,%6,%7}, {%8,%9}, {%0,%1,%2,%3};"
        : "+f"(d[0]), "+f"(d[1]), "+f"(d[2]), "+f"(d[3])
        : "r"(a[0]), "r"(a[1]), "r"(a[2]), "r"(a[3]), "r"(b0), "r"(b1));
}
__device__ __forceinline__ void sts128(uint32_t addr, uint32_t a, uint32_t b, uint32_t c, uint32_t d) {
    asm volatile("st.shared.v4.b32 [%0], {%1,%2,%3,%4};" :: "r"(addr), "r"(a), "r"(b), "r"(c), "r"(d) : "memory");
}

#define SW128(o) ((o) ^ (((o) >> 3) & 0x70))

// ============================================================================
// Stage-1 HMMA GEMM: part1[z][m][n] = sum_k x[m,k]*w_emb[n,k]
//   CTA 128x128, BK=64, 8 warps (warp 32x64), grid (32 m, 2 n, SPLITK z).
//   A path: LDG.128 x8 into regs (prefetched) -> in-reg fp16 split -> STS.
//   One __syncthreads per tile.
// ============================================================================
#define TK_     64
#define KSPAN   (V_ / SPLITK)       // 4096
#define NT_     (KSPAN / TK_)       // 64
#define AH_O    0
#define AL_O    16384
#define BH_O    32768
#define STG_SZ  49152               // Ah 16K + Al 16K + Bh 16K
#define SMEM_TOT (2 * STG_SZ)       // 98304

__global__ void __launch_bounds__(256, 1) gemm1_hmma_kernel(
    const float* __restrict__ x, const __half* __restrict__ wh,
    float* __restrict__ part1)
{
    extern __shared__ char smem[];
    const uint32_t sb = smem_u32(smem);
    const int tid = threadIdx.x;
    const int wid = tid >> 5;
    const int lane = tid & 31;

    const int m0 = blockIdx.x * 128;
    const int n0 = blockIdx.y * 128;
    const int z  = blockIdx.z;
    const int kbase = z * KSPAN;

    const int warp_m = wid & 3;
    const int warp_n = wid >> 2;

    float accm[2][8][4], accc[2][8][4];
    #pragma unroll
    for (int mt = 0; mt < 2; mt++)
        #pragma unroll
        for (int q = 0; q < 8; q++)
            #pragma unroll
            for (int r = 0; r < 4; r++) { accm[mt][q][r] = 0.f; accc[mt][q][r] = 0.f; }

    // A prefetch: 1024 pairs of float4 (each pair = 8 floats = 16B fp16 chunk).
    // pair p: row = p>>3, pch = p&7 (8 pairs per 64-col row). Thread owns p = tid + i*256.
    float4 xa[8];
    auto prefetchA = [&](int k0) {
        #pragma unroll
        for (int i = 0; i < 4; i++) {
            const int p = tid + i * 256;
            const int row = p >> 3, pch = p & 7;
            const float4* g = (const float4*)(x + (size_t)(m0 + row) * V_ + k0) + pch * 2;
            xa[2 * i]     = g[0];
            xa[2 * i + 1] = g[1];
        }
    };
    // convert regs -> Ah / Al(*4096) fp16 smem tiles
    auto convertA = [&](int s) {
        const uint32_t stg = sb + s * STG_SZ;
        #pragma unroll
        for (int i = 0; i < 4; i++) {
            const int p = tid + i * 256;
            const int row = p >> 3, pch = p & 7;
            const float f[8] = {xa[2*i].x, xa[2*i].y, xa[2*i].z, xa[2*i].w,
                                xa[2*i+1].x, xa[2*i+1].y, xa[2*i+1].z, xa[2*i+1].w};
            uint32_t hh[4], ll[4];
            #pragma unroll
            for (int q = 0; q < 4; q++) {
                __half2 H = __floats2half2_rn(f[2*q], f[2*q+1]);
                float r0 = (f[2*q]     - __low2float(H))  * 4096.f;
                float r1 = (f[2*q+1]   - __high2float(H)) * 4096.f;
                __half2 L = __floats2half2_rn(r0, r1);
                hh[q] = *(uint32_t*)&H;
                ll[q] = *(uint32_t*)&L;
            }
            const uint32_t off = SW128((uint32_t)(row * 128 + pch * 16));
            sts128(stg + AH_O + off, hh[0], hh[1], hh[2], hh[3]);
            sts128(stg + AL_O + off, ll[0], ll[1], ll[2], ll[3]);
        }
    };
    // B fp16 via cp.async: 128 rows x 64 fp16
    auto issue_B = [&](int s, int k0) {
        const uint32_t stg = sb + s * STG_SZ + BH_O;
        #pragma unroll
        for (int i = 0; i < 4; i++) {
            const int c = tid + i * 256;
            const int row = c >> 3, ch = c & 7;
            cp16(stg + SW128((uint32_t)(row * 128 + ch * 16)),
                 wh + (size_t)(n0 + row) * V_ + k0 + ch * 8);
        }
    };

    const int rowsel = lane & 15;
    const int khalf  = lane >> 4;

    prefetchA(kbase);
    issue_B(0, kbase);
    CP_COMMIT();

    for (int t = 0; t < NT_; t++) {
        const int s = t & 1;
        CP_WAIT(0);                 // B(t) landed
        convertA(s);                // stage s: last read at t-2, safe
        __syncthreads();            // STS visible; all warps past compute(t-1)
        if (t + 1 < NT_) {
            prefetchA(kbase + (t + 1) * TK_);
            issue_B(s ^ 1, kbase + (t + 1) * TK_);
            CP_COMMIT();
        }

        const uint32_t stg = sb + s * STG_SZ;
        #pragma unroll
        for (int k16 = 0; k16 < 4; k16++) {
            const uint32_t kb = (uint32_t)(k16 * 32 + khalf * 16);
            uint32_t ah[2][4], al[2][4], bh[4][4];
            #pragma unroll
            for (int mt = 0; mt < 2; mt++) {
                const uint32_t sw = SW128((uint32_t)((warp_m * 32 + mt * 16 + rowsel) * 128) + kb);
                ldsm4(ah[mt], stg + AH_O + sw);
                ldsm4(al[mt], stg + AL_O + sw);
            }
            #pragma unroll
            for (int nt = 0; nt < 4; nt++) {
                const uint32_t sw = SW128((uint32_t)((warp_n * 64 + nt * 16 + rowsel) * 128) + kb);
                ldsm4(bh[nt], stg + BH_O + sw);
            }
            #pragma unroll
            for (int mt = 0; mt < 2; mt++) {
                #pragma unroll
                for (int q = 0; q < 8; q++) {
                    const int nt = q >> 1, w = q & 1;
                    const uint32_t b0 = bh[nt][w], b1 = bh[nt][w + 2];
                    mma16816h(accm[mt][q], ah[mt], b0, b1);
                    mma16816h(accc[mt][q], al[mt], b0, b1);
                }
            }
        }
        // no trailing barrier: next iter's convert touches the other stage,
        // and the next barrier collectively fences compute(t) before B(t+2).
    }

    // ---- epilogue: D = accm + accc/4096 ----
    const int gid = lane >> 2;
    const int tig = lane & 3;
    const float inv = 1.f / 4096.f;
    float* base = part1 + (size_t)z * (M1_ * E_);
    #pragma unroll
    for (int mt = 0; mt < 2; mt++) {
        const int row0 = m0 + warp_m * 32 + mt * 16 + gid;
        #pragma unroll
        for (int q = 0; q < 8; q++) {
            const int col = n0 + warp_n * 64 + q * 8 + tig * 2;
            float d0 = fmaf(accc[mt][q][0], inv, accm[mt][q][0]);
            float d1 = fmaf(accc[mt][q][1], inv, accm[mt][q][1]);
            float d2 = fmaf(accc[mt][q][2], inv, accm[mt][q][2]);
            float d3 = fmaf(accc[mt][q][3], inv, accm[mt][q][3]);
            *(float2*)(base + (size_t)row0 * E_ + col)       = make_float2(d0, d1);
            *(float2*)(base + (size_t)(row0 + 8) * E_ + col) = make_float2(d2, d3);
        }
    }
}

// ---------------- convert w_emb fp32 -> fp16 ---------------------------------
__global__ void wconv_kernel(const float* __restrict__ in, __half* __restrict__ o, int n8)
{
    int i = blockIdx.x * blockDim.x + threadIdx.x;
    if (i >= n8) return;
    const float4* p = (const float4*)in;
    float4 a = p[2 * i], b = p[2 * i + 1];
    float v[8] = {a.x, a.y, a.z, a.w, b.x, b.y, b.z, b.w};
    union { __half e[8]; uint4 u; } H;
    #pragma unroll
    for (int q = 0; q < 8; q++) H.e[q] = __float2half_rn(v[q]);
    ((uint4*)o)[i] = H.u;
}

// ---------------- split-K reduce + bias + relu + rowsum ----------------------
__global__ void reduce1_kernel(const float* __restrict__ part,
                               const float* __restrict__ b_emb,
                               float* __restrict__ h, float* __restrict__ st)
{
    const int warp = (blockIdx.x * blockDim.x + threadIdx.x) >> 5;   // row 0..4095
    const int lane = threadIdx.x & 31;
    const size_t CH = (size_t)M1_ * E_;
    const float* p0 = part + (size_t)warp * E_;
    float sum = 0.f;
    #pragma unroll
    for (int i = 0; i < 8; i++) {
        const int col = lane + i * 32;
        float v = p0[col] + p0[CH + col] + b_emb[col];
        v = fmaxf(v, 0.f);
        h[(size_t)warp * E_ + col] = v;
        sum += v;
    }
    #pragma unroll
    for (int o = 16; o > 0; o >>= 1) sum += __shfl_xor_sync(0xFFFFFFFFu, sum, o);
    if (lane == 0) {
        const int b = warp >> 7;
        const int k = warp & (S_ - 1);
        st[k * B_ + b] = sum;
    }
}

// ---------------- generic fp32 NT GEMM (stages 4, 5a, 6) ---------------------
template<int BM, int BN, int BK, int TM, int TN>
__global__ void gemm_nt_kernel(const float* __restrict__ A, int lda, long sAz,
                               const float* __restrict__ B, int ldb, long sBz,
                               float* __restrict__ C, int ldc, long sCz,
                               const float* __restrict__ bias,
                               int K, int do_relu)
{
    constexpr int THREADS = (BM * BN) / (TM * TN);
    constexpr int LA = (BM * BK) / THREADS;
    constexpr int LB = (BN * BK) / THREADS;
    constexpr int TX = BN / TN;

    __shared__ float As[BK][BM + 4];
    __shared__ float Bs[BK][BN + 4];

    const long z = blockIdx.z;
    A += z * sAz;  B += z * sBz;  C += z * sCz;

    const int m0 = blockIdx.x * BM;
    const int n0 = blockIdx.y * BN;
    const int tid = threadIdx.x;
    const int tx = tid % TX;
    const int ty = tid / TX;

    float acc[TM][TN];
    #pragma unroll
    for (int i = 0; i < TM; i++)
        #pragma unroll
        for (int j = 0; j < TN; j++) acc[i][j] = 0.f;

    float ra[LA], rb[LB];
    const int nTiles = K / BK;

    #pragma unroll
    for (int u = 0; u < LA; u++) {
        int idx = tid + u * THREADS;
        ra[u] = A[(long)(m0 + idx / BK) * lda + (idx % BK)];
    }
    #pragma unroll
    for (int u = 0; u < LB; u++) {
        int idx = tid + u * THREADS;
        rb[u] = B[(long)(n0 + idx / BK) * ldb + (idx % BK)];
    }
    #pragma unroll
    for (int u = 0; u < LA; u++) {
        int idx = tid + u * THREADS;
        As[idx % BK][idx / BK] = ra[u];
    }
    #pragma unroll
    for (int u = 0; u < LB; u++) {
        int idx = tid + u * THREADS;
        Bs[idx % BK][idx / BK] = rb[u];
    }
    __syncthreads();

    for (int t = 0; t < nTiles; t++) {
        const int k_next = (t + 1) * BK;
        const bool have_next = (t + 1) < nTiles;
        if (have_next) {
            #pragma unroll
            for (int u = 0; u < LA; u++) {
                int idx = tid + u * THREADS;
                ra[u] = A[(long)(m0 + idx / BK) * lda + k_next + (idx % BK)];
            }
            #pragma unroll
            for (int u = 0; u < LB; u++) {
                int idx = tid + u * THREADS;
                rb[u] = B[(long)(n0 + idx / BK) * ldb + k_next + (idx % BK)];
            }
        }

        #pragma unroll
        for (int kk = 0; kk < BK; kk++) {
            float a[TM], b[TN];
            #pragma unroll
            for (int i = 0; i < TM; i++) a[i] = As[kk][ty * TM + i];
            #pragma unroll
            for (int j = 0; j < TN; j++) b[j] = Bs[kk][tx * TN + j];
            #pragma unroll
            for (int i = 0; i < TM; i++)
                #pragma unroll
                for (int j = 0; j < TN; j++)
                    acc[i][j] = fmaf(a[i], b[j], acc[i][j]);
        }
        __syncthreads();

        if (have_next) {
            #pragma unroll
            for (int u = 0; u < LA; u++) {
                int idx = tid + u * THREADS;
                As[idx % BK][idx / BK] = ra[u];
            }
            #pragma unroll
            for (int u = 0; u < LB; u++) {
                int idx = tid + u * THREADS;
                Bs[idx % BK][idx / BK] = rb[u];
            }
            __syncthreads();
        }
    }

    #pragma unroll
    for (int i = 0; i < TM; i++) {
        const int m = m0 + ty * TM + i;
        #pragma unroll
        for (int j = 0; j < TN; j++) {
            const int n = n0 + tx * TN + j;
            float v = acc[i][j];
            if (bias) v += bias[n];
            if (do_relu) v = fmaxf(v, 0.f);
            C[(long)m * ldc + n] = v;
        }
    }
}

// ---------------- Weff[b,e,j] = sum_k w_red[e, k*E+j] * s[b,k] ---------------
// batched loads (MLP=8) to fix the latency-bound 1TB/s observed in ncu
__global__ void weff_kernel(const float* __restrict__ w_red,
                            const float* __restrict__ st,
                            float* __restrict__ weff)
{
    __shared__ float4 s_sm[S_ * (B_ / 4)];
    const int e = blockIdx.x;
    const int j = threadIdx.x;

    for (int idx = threadIdx.x; idx < S_ * B_; idx += blockDim.x)
        ((float*)s_sm)[idx] = st[idx];
    __syncthreads();

    float acc[B_];
    #pragma unroll
    for (int b = 0; b < B_; b++) acc[b] = 0.f;

    const float* wp = w_red + (long)e * (S_ * E_) + j;
    for (int k0 = 0; k0 < S_; k0 += 8) {
        float wv[8];
        #pragma unroll
        for (int u = 0; u < 8; u++)          // batch loads first -> 8 in flight
            wv[u] = wp[(k0 + u) * E_];
        #pragma unroll
        for (int u = 0; u < 8; u++) {
            const float w = wv[u];
            #pragma unroll
            for (int bb = 0; bb < B_ / 4; bb++) {
                const float4 sv = s_sm[(k0 + u) * (B_ / 4) + bb];
                acc[bb * 4 + 0] = fmaf(w, sv.x, acc[bb * 4 + 0]);
                acc[bb * 4 + 1] = fmaf(w, sv.y, acc[bb * 4 + 1]);
                acc[bb * 4 + 2] = fmaf(w, sv.z, acc[bb * 4 + 2]);
                acc[bb * 4 + 3] = fmaf(w, sv.w, acc[bb * 4 + 3]);
            }
        }
    }
    #pragma unroll
    for (int b = 0; b < B_; b++)
        weff[(long)b * (E_ * E_) + e * E_ + j] = acc[b];
}

// ---------------- y2 split-K reduce + bias + relu ----------------------------
__global__ void reduce5_kernel(const float* __restrict__ part,
                               const float* __restrict__ b_red2,
                               float* __restrict__ y2)
{
    const int idx = blockIdx.x * blockDim.x + threadIdx.x;
    float v = 0.f;
    #pragma unroll 8
    for (int z = 0; z < 128; z++) v += part[z * (B_ * E_) + idx];
    v += b_red2[idx & (E_ - 1)];
    y2[idx] = fmaxf(v, 0.f);
}

// ---------------- launch -----------------------------------------------------
extern "C" void kernel_launch(void* const* d_in, const int* in_sizes, int n_in,
                              void* d_out, int out_size)
{
    const float* x      = (const float*)d_in[0];
    const float* w_emb  = (const float*)d_in[1];
    const float* b_emb  = (const float*)d_in[2];
    const float* w_red  = (const float*)d_in[3];
    const float* b_red  = (const float*)d_in[4];
    const float* w_red2 = (const float*)d_in[5];
    const float* b_red2 = (const float*)d_in[6];
    const float* w_out  = (const float*)d_in[7];
    const float* b_out  = (const float*)d_in[8];
    float* out = (float*)d_out;

    __half *wh_p;
    float *part1_p, *h_p, *st_p, *weff_p, *y_p, *part_p, *y2_p;
    cudaGetSymbolAddress((void**)&wh_p,    g_wh);
    cudaGetSymbolAddress((void**)&part1_p, g_part1);
    cudaGetSymbolAddress((void**)&h_p,     g_h);
    cudaGetSymbolAddress((void**)&st_p,    g_st);
    cudaGetSymbolAddress((void**)&weff_p,  g_weff);
    cudaGetSymbolAddress((void**)&y_p,     g_y);
    cudaGetSymbolAddress((void**)&part_p,  g_part);
    cudaGetSymbolAddress((void**)&y2_p,    g_y2);

    cudaFuncSetAttribute(gemm1_hmma_kernel,
                         cudaFuncAttributeMaxDynamicSharedMemorySize, SMEM_TOT);

    // Stage 1a: w_emb -> fp16
    wconv_kernel<<<(E_ * V_ / 8 + 255) / 256, 256>>>(w_emb, wh_p, E_ * V_ / 8);

    // Stage 1b: HMMA fp16 2-pass GEMM (register-staged A split) -> partials
    gemm1_hmma_kernel<<<dim3(M1_ / 128, E_ / 128, SPLITK), 256, SMEM_TOT>>>(
        x, wh_p, part1_p);

    // Stage 1c/2: reduce partials + bias + relu -> h ; rowsum -> st
    reduce1_kernel<<<M1_ / 8, 256>>>(part1_p, b_emb, h_p, st_p);

    // Stage 3: Weff
    weff_kernel<<<E_, 256>>>(w_red, st_p, weff_p);

    // Stage 4: y = relu(batched h_b @ Weff_b^T + b_red)
    gemm_nt_kernel<128, 64, 16, 8, 4><<<dim3(1, 4, B_), 256>>>(
        h_p, E_, (long)S_ * E_,
        weff_p, E_, (long)E_ * E_,
        y_p, E_, (long)S_ * E_,
        b_red, E_, 1);

    // Stage 5a: y2 partials, split-K over K=32768 into 128 chunks of 256
    gemm_nt_kernel<32, 64, 16, 2, 4><<<dim3(1, 4, 128), 256>>>(
        y_p, S_ * E_, 256,
        w_red2, S_ * E_, 256,
        part_p, E_, (long)B_ * E_,
        nullptr, 256, 0);

    // Stage 5b: reduce + bias + relu
    reduce5_kernel<<<(B_ * E_) / 256, 256>>>(part_p, b_red2, y2_p);

    // Stage 6: out = y2 @ w_out^T + b_out
    gemm_nt_kernel<32, 64, 16, 2, 4><<<dim3(1, V_ / 64, 1), 256>>>(
        y2_p, E_, 0, w_out, E_, 0, out, V_, 0, b_out, E_, 0);
}